// round 11
// baseline (speedup 1.0000x reference)
#include <cuda_runtime.h>
#include <cuda_bf16.h>
#include <math.h>

#define NBATCH 8
#define NPTS 256
#define NRBF_ 50
#define NK 255
#define SD 8960
#define NSITES 2048

__device__ float g_vx[NSITES * 3];
__device__ float g_tr[NSITES];

// ---- smem word offsets ----
#define W_AH  0        // A hi: 256 rows x 33 (32 kp words + pad)
#define W_AL  8448
#define W_B   16896    // 8 regions (4 panels x hi/lo) x 4608 (128 h x 36)
#define W_CPK 53760    // float4[128] {c1,c2,cf,0}
#define W_WS  54272    // float2[128] {s1W2,s2W2}
#define W_XS  54528    // float[768]
#define W_FS  55296    // float[32]
#define W_SMX 55328    // float[32]
#define W_MUS 55360    // float[64]
#define W_HS  55424    // float[8*128] per-warp silu(zf) col sums
#define W_RED 56448    // float[8*8]
#define W_TOT 56512    // float[8]
#define SMEM_WORDS 56520  // 226080 bytes

static __device__ __forceinline__ unsigned pack_bf2(float a, float b) {
  unsigned short ha = __bfloat16_as_ushort(__float2bfloat16(a));
  unsigned short hb = __bfloat16_as_ushort(__float2bfloat16(b));
  return (unsigned)ha | ((unsigned)hb << 16);
}
static __device__ __forceinline__ float sgm(float z) {  // sigmoid via 1 MUFU
  float t;
  asm("tanh.approx.f32 %0, %1;" : "=f"(t) : "f"(0.5f * z));
  return fmaf(0.5f, t, 0.5f);
}
static __device__ __forceinline__ void mma4(float* c, const unsigned* a,
                                            unsigned b0, unsigned b1) {
  asm volatile(
      "mma.sync.aligned.m16n8k16.row.col.f32.bf16.bf16.f32 "
      "{%0,%1,%2,%3},{%4,%5,%6,%7},{%8,%9},{%0,%1,%2,%3};"
      : "+f"(c[0]), "+f"(c[1]), "+f"(c[2]), "+f"(c[3])
      : "r"(a[0]), "r"(a[1]), "r"(a[2]), "r"(a[3]), "r"(b0), "r"(b1));
}

__global__ __launch_bounds__(256, 1) void fd_main(
    const float* __restrict__ state, const float* __restrict__ mus,
    const float* __restrict__ gamma_p,
    const float* __restrict__ s1W1, const float* __restrict__ s1b1,
    const float* __restrict__ s1W2, const float* __restrict__ s1b2,
    const float* __restrict__ s2W1, const float* __restrict__ s2b1,
    const float* __restrict__ s2W2, const float* __restrict__ s2b2,
    const float* __restrict__ fW1, const float* __restrict__ fb1,
    const float* __restrict__ fW2, const float* __restrict__ fb2,
    float* __restrict__ out)
{
  extern __shared__ float smf[];
  unsigned* smu = (unsigned*)smf;
  const int tid = threadIdx.x, wid = tid >> 5, lane = tid & 31;
  const int g = lane >> 2, t4 = lane & 3;
  const int bi = blockIdx.x, b = bi >> 8, i = bi & 255;
  const float gam = gamma_p[0];
  const float b2s1 = s1b2[0], b2s2 = s2b2[0];

  // ---- stage B panels: p0=W1, p1=mu*W1, p2=W2, p3=WF; hi/lo; k-pair packed ----
  for (int idx = tid; idx < 16384; idx += 256) {
    int kp = idx & 31, h = (idx >> 5) & 127, p = idx >> 12;
    const float* src = (p <= 1) ? s1W1 : (p == 2 ? s2W1 : fW1);
    int m0 = 2 * kp, m1 = m0 + 1;
    float f0 = (m0 < NRBF_) ? src[m0 * 128 + h] : 0.f;
    float f1 = (m1 < NRBF_) ? src[m1 * 128 + h] : 0.f;
    if (p == 1) { f0 *= (m0 < NRBF_) ? mus[m0] : 0.f; f1 *= (m1 < NRBF_) ? mus[m1] : 0.f; }
    float h0 = __bfloat162float(__float2bfloat16(f0));
    float h1 = __bfloat162float(__float2bfloat16(f1));
    smu[W_B + (p * 2 + 0) * 4608 + h * 36 + kp] = pack_bf2(h0, h1);
    smu[W_B + (p * 2 + 1) * 4608 + h * 36 + kp] = pack_bf2(f0 - h0, f1 - h1);
  }
  if (tid < 128) ((float2*)(smf + W_WS))[tid] = make_float2(s1W2[tid], s2W2[tid]);
  for (int idx = tid; idx < 768; idx += 256) smf[W_XS + idx] = state[b * SD + idx];
  if (tid < 64) smf[W_MUS + tid] = (tid < NRBF_) ? mus[tid] : 0.f;
  for (int idx = tid; idx < 1024; idx += 256) smf[W_HS + idx] = 0.f;
  if (tid < 32) {
    float v = state[b * SD + 768 + i * 32 + tid];
    smf[W_FS + tid] = v;
    float mx = v;
    #pragma unroll
    for (int o = 16; o; o >>= 1) mx = fmaxf(mx, __shfl_xor_sync(0xffffffffu, mx, o));
    float e = __expf(v - mx), s = e;
    #pragma unroll
    for (int o = 16; o; o >>= 1) s += __shfl_xor_sync(0xffffffffu, s, o);
    smf[W_SMX + tid] = __fdividef(e, s);
  }
  __syncthreads();

  // ---- per-(b,i) constant hidden contributions ----
  if (tid < 128) {
    const int h = tid;
    float c1 = s1b1[h], c2 = s2b1[h], cf = fb1[h];
    #pragma unroll 4
    for (int f = 0; f < 32; f++) {
      float fv = smf[W_FS + f];
      c1 = fmaf(fv, s1W1[(50 + f) * 128 + h] + s1W1[(82 + f) * 128 + h], c1);
      c2 = fmaf(fv, s2W1[(50 + f) * 128 + h] + s2W1[(82 + f) * 128 + h], c2);
      cf = fmaf(smf[W_SMX + f], fW1[(50 + f) * 128 + h], cf);
    }
    ((float4*)(smf + W_CPK))[h] = make_float4(c1, c2, cf, 0.f);
  }
  // ---- build A tile: row tid = neighbor (row 255 zeroed) ----
  {
    const float aact = (tid < NK) ? 1.f : 0.f;
    const int k = (tid < NK) ? tid : NK - 1;
    const int j = (k < i) ? k : k + 1;
    float rx = smf[W_XS + i * 3 + 0] - smf[W_XS + j * 3 + 0];
    float ry = smf[W_XS + i * 3 + 1] - smf[W_XS + j * 3 + 1];
    float rz = smf[W_XS + i * 3 + 2] - smf[W_XS + j * 3 + 2];
    float dl = sqrtf(rx * rx + ry * ry + rz * rz + 1e-6f);
    #pragma unroll
    for (int kp = 0; kp < 32; kp++) {
      int m0 = 2 * kp, m1 = m0 + 1;
      float f0 = 0.f, f1 = 0.f;
      if (m0 < NRBF_) { float dm = dl - smf[W_MUS + m0]; f0 = __expf(-gam * dm * dm) * aact; }
      if (m1 < NRBF_) { float dm = dl - smf[W_MUS + m1]; f1 = __expf(-gam * dm * dm) * aact; }
      float h0 = __bfloat162float(__float2bfloat16(f0));
      float h1 = __bfloat162float(__float2bfloat16(f1));
      smu[W_AH + tid * 33 + kp] = pack_bf2(h0, h1);
      smu[W_AL + tid * 33 + kp] = pack_bf2(f0 - h0, f1 - h1);
    }
  }
  __syncthreads();

  // ---- per-lane row geometry (4 slots: mtile*2 + rowhalf) ----
  float rxv[4], ryv[4], rzv[4], rr2v[4], dlv[4], akv[4];
  #pragma unroll
  for (int s = 0; s < 4; s++) {
    int row = wid * 32 + (s >> 1) * 16 + (s & 1) * 8 + g;
    akv[s] = (row < NK) ? 1.f : 0.f;
    int kk = (row < NK) ? row : NK - 1;
    int j = (kk < i) ? kk : kk + 1;
    rxv[s] = smf[W_XS + i * 3 + 0] - smf[W_XS + j * 3 + 0];
    ryv[s] = smf[W_XS + i * 3 + 1] - smf[W_XS + j * 3 + 1];
    rzv[s] = smf[W_XS + i * 3 + 2] - smf[W_XS + j * 3 + 2];
    rr2v[s] = rxv[s] * rxv[s] + ryv[s] * ryv[s] + rzv[s] * rzv[s];
    dlv[s] = sqrtf(rr2v[s] + 1e-6f);
  }

  // ---- load A fragments (resident): [mtile][ks][4] hi/lo ----
  unsigned Ah[2][4][4], Al[2][4][4];
  #pragma unroll
  for (int m = 0; m < 2; m++)
    #pragma unroll
    for (int ks = 0; ks < 4; ks++) {
      int r0 = (wid * 32 + m * 16 + g) * 33 + ks * 8 + t4;
      int r1 = r0 + 8 * 33;
      Ah[m][ks][0] = smu[W_AH + r0]; Ah[m][ks][1] = smu[W_AH + r1];
      Ah[m][ks][2] = smu[W_AH + r0 + 4]; Ah[m][ks][3] = smu[W_AH + r1 + 4];
      Al[m][ks][0] = smu[W_AL + r0]; Al[m][ks][1] = smu[W_AL + r1];
      Al[m][ks][2] = smu[W_AL + r0 + 4]; Al[m][ks][3] = smu[W_AL + r1 + 4];
    }

  float s1p[4] = {0, 0, 0, 0}, dap[4] = {0, 0, 0, 0}, s2p[4] = {0, 0, 0, 0};

  // ---- main loop: h in chunks of 16, panels in pairs ----
  #pragma unroll 1
  for (int hc = 0; hc < 8; hc++) {
    float4 cpk[4]; float2 wsv[4];
    #pragma unroll
    for (int cc = 0; cc < 4; cc++) {
      int h = hc * 16 + (cc >> 1) * 8 + t4 * 2 + (cc & 1);
      cpk[cc] = ((const float4*)(smf + W_CPK))[h];
      wsv[cc] = ((const float2*)(smf + W_WS))[h];
    }
    #pragma unroll 1
    for (int pg = 0; pg < 2; pg++) {
      float C0[2][2][4], C1[2][2][4];
      #pragma unroll
      for (int m = 0; m < 2; m++)
        #pragma unroll
        for (int nt = 0; nt < 2; nt++)
          #pragma unroll
          for (int q = 0; q < 4; q++) { C0[m][nt][q] = 0.f; C1[m][nt][q] = 0.f; }
      #pragma unroll
      for (int ks = 0; ks < 4; ks++) {
        unsigned bh0[2][2], bh1[2][2], bl0[2][2], bl1[2][2];
        #pragma unroll
        for (int pl = 0; pl < 2; pl++)
          #pragma unroll
          for (int nt = 0; nt < 2; nt++) {
            int base = W_B + ((pg * 2 + pl) * 2) * 4608 + (hc * 16 + nt * 8 + g) * 36 + ks * 8 + t4;
            bh0[pl][nt] = smu[base]; bh1[pl][nt] = smu[base + 4];
            bl0[pl][nt] = smu[base + 4608]; bl1[pl][nt] = smu[base + 4608 + 4];
          }
        #pragma unroll
        for (int m = 0; m < 2; m++)
          #pragma unroll
          for (int nt = 0; nt < 2; nt++) {
            mma4(C0[m][nt], Ah[m][ks], bh0[0][nt], bh1[0][nt]);
            mma4(C0[m][nt], Ah[m][ks], bl0[0][nt], bl1[0][nt]);
            mma4(C0[m][nt], Al[m][ks], bh0[0][nt], bh1[0][nt]);
            mma4(C1[m][nt], Ah[m][ks], bh0[1][nt], bh1[1][nt]);
            mma4(C1[m][nt], Ah[m][ks], bl0[1][nt], bl1[1][nt]);
            mma4(C1[m][nt], Al[m][ks], bh0[1][nt], bh1[1][nt]);
          }
      }
      if (pg == 0) {  // C0 = A1 (s1 pre-act), C1 = AM (mu-weighted)
        #pragma unroll
        for (int m = 0; m < 2; m++)
          #pragma unroll
          for (int nt = 0; nt < 2; nt++)
            #pragma unroll
            for (int q = 0; q < 2; q++) {
              int cc = nt * 2 + q;
              float c1h = cpk[cc].x, w21 = wsv[cc].x;
              {
                int s = m * 2;
                float a1 = C0[m][nt][q], am = C1[m][nt][q];
                float z = a1 + c1h, sg = sgm(z);
                s1p[s] = fmaf(z * sg, w21, s1p[s]);
                float sp = sg * fmaf(z, 1.f - sg, 1.f);
                dap[s] = fmaf(w21 * sp, fmaf(dlv[s], a1, -am), dap[s]);
              }
              {
                int s = m * 2 + 1;
                float a1 = C0[m][nt][q + 2], am = C1[m][nt][q + 2];
                float z = a1 + c1h, sg = sgm(z);
                s1p[s] = fmaf(z * sg, w21, s1p[s]);
                float sp = sg * fmaf(z, 1.f - sg, 1.f);
                dap[s] = fmaf(w21 * sp, fmaf(dlv[s], a1, -am), dap[s]);
              }
            }
      } else {  // C0 = s2 pre-act, C1 = f pre-act
        float colsum[4] = {0.f, 0.f, 0.f, 0.f};
        #pragma unroll
        for (int m = 0; m < 2; m++)
          #pragma unroll
          for (int nt = 0; nt < 2; nt++)
            #pragma unroll
            for (int q = 0; q < 2; q++) {
              int cc = nt * 2 + q;
              float c2h = cpk[cc].y, cfh = cpk[cc].z, w22 = wsv[cc].y;
              {
                int s = m * 2;
                float z2 = C0[m][nt][q] + c2h, sg2 = sgm(z2);
                s2p[s] = fmaf(z2 * sg2, w22, s2p[s]);
                float zf = C1[m][nt][q] + cfh, sgf = sgm(zf);
                colsum[cc] = fmaf(zf * sgf, akv[s], colsum[cc]);
              }
              {
                int s = m * 2 + 1;
                float z2 = C0[m][nt][q + 2] + c2h, sg2 = sgm(z2);
                s2p[s] = fmaf(z2 * sg2, w22, s2p[s]);
                float zf = C1[m][nt][q + 2] + cfh, sgf = sgm(zf);
                colsum[cc] = fmaf(zf * sgf, akv[s], colsum[cc]);
              }
            }
        #pragma unroll
        for (int cc = 0; cc < 4; cc++) {
          float v = colsum[cc];
          v += __shfl_xor_sync(0xffffffffu, v, 4);
          v += __shfl_xor_sync(0xffffffffu, v, 8);
          v += __shfl_xor_sync(0xffffffffu, v, 16);
          colsum[cc] = v;
        }
        if (g == 0) {
          #pragma unroll
          for (int cc = 0; cc < 4; cc++) {
            int h = hc * 16 + (cc >> 1) * 8 + t4 * 2 + (cc & 1);
            smf[W_HS + wid * 128 + h] += colsum[cc];
          }
        }
      }
    }
  }

  // ---- reduce partials over the 4 lanes sharing each row ----
  #pragma unroll
  for (int s = 0; s < 4; s++) {
    s1p[s] += __shfl_xor_sync(0xffffffffu, s1p[s], 1);
    s1p[s] += __shfl_xor_sync(0xffffffffu, s1p[s], 2);
    dap[s] += __shfl_xor_sync(0xffffffffu, dap[s], 1);
    dap[s] += __shfl_xor_sync(0xffffffffu, dap[s], 2);
    s2p[s] += __shfl_xor_sync(0xffffffffu, s2p[s], 1);
    s2p[s] += __shfl_xor_sync(0xffffffffu, s2p[s], 2);
  }
  float vals[7] = {0.f, 0.f, 0.f, 0.f, 0.f, 0.f, 0.f};
  if (t4 == 0) {
    #pragma unroll
    for (int s = 0; s < 4; s++) {
      float s1v = s1p[s] + b2s1;
      float s2v = s2p[s] + b2s2;
      float gd = -2.f * gam * dap[s] * __fdividef(rr2v[s], dlv[s]);
      float a = akv[s];
      vals[0] = fmaf(a * s1v, rxv[s], vals[0]);
      vals[1] = fmaf(a * s1v, ryv[s], vals[1]);
      vals[2] = fmaf(a * s1v, rzv[s], vals[2]);
      vals[3] = fmaf(a * s2v, rxv[s], vals[3]);
      vals[4] = fmaf(a * s2v, ryv[s], vals[4]);
      vals[5] = fmaf(a * s2v, rzv[s], vals[5]);
      vals[6] += a * (gd + 3.f * s1v);
    }
  }
  #pragma unroll
  for (int c = 0; c < 7; c++) {
    float v = vals[c];
    #pragma unroll
    for (int o = 16; o; o >>= 1) v += __shfl_xor_sync(0xffffffffu, v, o);
    vals[c] = v;
  }
  if (lane == 0) {
    #pragma unroll
    for (int c = 0; c < 7; c++) smf[W_RED + wid * 8 + c] = vals[c];
  }
  __syncthreads();
  if (tid < 7) {
    float s = 0.f;
    #pragma unroll
    for (int w = 0; w < 8; w++) s += smf[W_RED + w * 8 + tid];
    smf[W_TOT + tid] = s;
  }
  __syncthreads();
  if (tid == 0) {
    const float inv = 1.f / (float)NK;
    float v1x = smf[W_TOT + 0] * inv, v1y = smf[W_TOT + 1] * inv, v1z = smf[W_TOT + 2] * inv;
    float m2x = smf[W_TOT + 3] * inv, m2y = smf[W_TOT + 4] * inv, m2z = smf[W_TOT + 5] * inv;
    g_vx[bi * 3 + 0] = v1x + (m2y * v1z - m2z * v1y);
    g_vx[bi * 3 + 1] = v1y + (m2z * v1x - m2x * v1z);
    g_vx[bi * 3 + 2] = v1z + (m2x * v1y - m2y * v1x);
    g_tr[bi] = smf[W_TOT + 6];
  }
  // v_feats = (mean_k silu(zf)) @ fW2 + fb2
  if (tid < 32) {
    float acc = 0.f;
    #pragma unroll 4
    for (int h = 0; h < 128; h++) {
      float hs = 0.f;
      #pragma unroll
      for (int w = 0; w < 8; w++) hs += smf[W_HS + w * 128 + h];
      acc = fmaf(hs, fW2[h * 32 + tid], acc);
    }
    out[b * SD + 768 + i * 32 + tid] = acc * (1.f / (float)NK) + fb2[tid];
  }
}

__global__ __launch_bounds__(256) void fd_final(float* __restrict__ out)
{
  __shared__ float red[8][4];
  __shared__ float tot[4];
  const int b = blockIdx.x, tid = threadIdx.x;
  const float v0 = g_vx[(b * NPTS + tid) * 3 + 0];
  const float v1 = g_vx[(b * NPTS + tid) * 3 + 1];
  const float v2 = g_vx[(b * NPTS + tid) * 3 + 2];
  const float v3 = g_tr[b * NPTS + tid];
  float r0 = v0, r1 = v1, r2 = v2, r3 = v3;
  #pragma unroll
  for (int o = 16; o; o >>= 1) {
    r0 += __shfl_xor_sync(0xffffffffu, r0, o);
    r1 += __shfl_xor_sync(0xffffffffu, r1, o);
    r2 += __shfl_xor_sync(0xffffffffu, r2, o);
    r3 += __shfl_xor_sync(0xffffffffu, r3, o);
  }
  const int wid = tid >> 5, lane = tid & 31;
  if (lane == 0) { red[wid][0] = r0; red[wid][1] = r1; red[wid][2] = r2; red[wid][3] = r3; }
  __syncthreads();
  if (tid < 4) {
    float s = 0.f;
    #pragma unroll
    for (int w = 0; w < 8; w++) s += red[w][tid];
    tot[tid] = s;
  }
  __syncthreads();
  const float invn = 1.f / (float)NPTS;
  out[b * SD + tid * 3 + 0] = v0 - tot[0] * invn;
  out[b * SD + tid * 3 + 1] = v1 - tot[1] * invn;
  out[b * SD + tid * 3 + 2] = v2 - tot[2] * invn;
  if (tid == 0) out[NBATCH * SD + b] = tot[3] * (1.f / (float)NK);
}

extern "C" void kernel_launch(void* const* d_in, const int* in_sizes, int n_in,
                              void* d_out, int out_size)
{
  const float* state = (const float*)d_in[1];
  const float* mus   = (const float*)d_in[2];
  const float* gam   = (const float*)d_in[3];
  const float* s1W1  = (const float*)d_in[4];
  const float* s1b1  = (const float*)d_in[5];
  const float* s1W2  = (const float*)d_in[6];
  const float* s1b2  = (const float*)d_in[7];
  const float* s2W1  = (const float*)d_in[8];
  const float* s2b1  = (const float*)d_in[9];
  const float* s2W2  = (const float*)d_in[10];
  const float* s2b2  = (const float*)d_in[11];
  const float* fW1   = (const float*)d_in[12];
  const float* fb1   = (const float*)d_in[13];
  const float* fW2   = (const float*)d_in[14];
  const float* fb2   = (const float*)d_in[15];
  float* out = (float*)d_out;

  const int smem_bytes = SMEM_WORDS * (int)sizeof(float);
  cudaFuncSetAttribute(fd_main, cudaFuncAttributeMaxDynamicSharedMemorySize, smem_bytes);
  fd_main<<<NSITES, 256, smem_bytes>>>(
      state, mus, gam,
      s1W1, s1b1, s1W2, s1b2,
      s2W1, s2b1, s2W2, s2b2,
      fW1, fb1, fW2, fb2, out);
  fd_final<<<NBATCH, 256>>>(out);
}